// round 15
// baseline (speedup 1.0000x reference)
#include <cuda_runtime.h>
#include <math.h>
#include <cstdint>

// Problem constants
#define B_   4
#define N_   10000
#define E_   100000
#define H_   8
#define FIN_ 256
#define M_TOTAL 40000

// GEMM tiling
#define BM 128
#define BN 128
#define BK 16

// -------------------- scratch (device globals) ------------------------------
__device__ float g_proj  [M_TOTAL * FIN_];
__device__ float g_numer [M_TOTAL * FIN_];
__device__ float g_relagg[M_TOTAL * FIN_];
__device__ float g_pre   [M_TOTAL * FIN_];
__device__ float g_ssrc  [M_TOTAL * H_];
__device__ float g_strg  [M_TOTAL * H_];
__device__ int   g_cnt   [M_TOTAL];
__device__ int   g_rowptr[M_TOTAL];
__device__ int   g_cursor[M_TOTAL];
__device__ int2  g_elist [B_ * E_];     // (edge id, src) sorted by trg

// -------------------- f32x2 packed helpers ----------------------------------
__device__ __forceinline__ unsigned long long pack2(float x, float y) {
    unsigned long long r;
    asm("mov.b64 %0, {%1, %2};" : "=l"(r) : "f"(x), "f"(y));
    return r;
}
__device__ __forceinline__ void unpack2(unsigned long long v, float& x, float& y) {
    asm("mov.b64 {%0, %1}, %2;" : "=f"(x), "=f"(y) : "l"(v));
}
__device__ __forceinline__ void fma2(unsigned long long& d,
                                     unsigned long long a, unsigned long long b) {
    asm("fma.rn.f32x2 %0, %1, %2, %0;" : "+l"(d) : "l"(a), "l"(b));
}

// -------------------- GEMM core ---------------------------------------------
struct SmemGemm {
    float As[2][BK][BM];
    float Bs[2][BK][BN];
};  // 32768 bytes

__device__ __forceinline__ void gemm_tile(const float* __restrict__ A,
                                          const float* __restrict__ Wt,
                                          int bm, int bn, SmemGemm& S,
                                          float acc[8][8]) {
    const int t  = threadIdx.x;
    const int lr = t & 127, lk = (t >> 7) * 8;
    const int ty = t >> 4,  tx = t & 15;

    const bool aval = (bm + lr) < M_TOTAL;
    const float* Arow = A  + (size_t)(bm + lr) * FIN_ + lk;
    const float* Brow = Wt + (size_t)(bn + lr) * FIN_ + lk;

    const float4 fz = make_float4(0.f, 0.f, 0.f, 0.f);
    float4 ra0 = aval ? *reinterpret_cast<const float4*>(Arow)     : fz;
    float4 ra1 = aval ? *reinterpret_cast<const float4*>(Arow + 4) : fz;
    float4 rb0 = *reinterpret_cast<const float4*>(Brow);
    float4 rb1 = *reinterpret_cast<const float4*>(Brow + 4);

    unsigned long long acc2[4][8];
    #pragma unroll
    for (int p = 0; p < 4; p++)
        #pragma unroll
        for (int j = 0; j < 8; j++) acc2[p][j] = 0ull;

    S.As[0][lk + 0][lr] = ra0.x; S.As[0][lk + 1][lr] = ra0.y;
    S.As[0][lk + 2][lr] = ra0.z; S.As[0][lk + 3][lr] = ra0.w;
    S.As[0][lk + 4][lr] = ra1.x; S.As[0][lk + 5][lr] = ra1.y;
    S.As[0][lk + 6][lr] = ra1.z; S.As[0][lk + 7][lr] = ra1.w;
    S.Bs[0][lk + 0][lr] = rb0.x; S.Bs[0][lk + 1][lr] = rb0.y;
    S.Bs[0][lk + 2][lr] = rb0.z; S.Bs[0][lk + 3][lr] = rb0.w;
    S.Bs[0][lk + 4][lr] = rb1.x; S.Bs[0][lk + 5][lr] = rb1.y;
    S.Bs[0][lk + 6][lr] = rb1.z; S.Bs[0][lk + 7][lr] = rb1.w;
    __syncthreads();

    #pragma unroll 1
    for (int kb = 0; kb < FIN_ / BK; kb++) {
        const int buf = kb & 1;
        if (kb < FIN_ / BK - 1) {
            const float* An = Arow + (kb + 1) * BK;
            const float* Bn = Brow + (kb + 1) * BK;
            ra0 = aval ? *reinterpret_cast<const float4*>(An)     : fz;
            ra1 = aval ? *reinterpret_cast<const float4*>(An + 4) : fz;
            rb0 = *reinterpret_cast<const float4*>(Bn);
            rb1 = *reinterpret_cast<const float4*>(Bn + 4);
        }
        #pragma unroll
        for (int k = 0; k < BK; k++) {
            float4 a0 = *reinterpret_cast<const float4*>(&S.As[buf][k][ty * 4]);
            float4 a1 = *reinterpret_cast<const float4*>(&S.As[buf][k][64 + ty * 4]);
            float4 b0 = *reinterpret_cast<const float4*>(&S.Bs[buf][k][tx * 4]);
            float4 b1 = *reinterpret_cast<const float4*>(&S.Bs[buf][k][64 + tx * 4]);
            unsigned long long ap[4];
            ap[0] = pack2(a0.x, a0.y); ap[1] = pack2(a0.z, a0.w);
            ap[2] = pack2(a1.x, a1.y); ap[3] = pack2(a1.z, a1.w);
            unsigned long long bd[8];
            bd[0] = pack2(b0.x, b0.x); bd[1] = pack2(b0.y, b0.y);
            bd[2] = pack2(b0.z, b0.z); bd[3] = pack2(b0.w, b0.w);
            bd[4] = pack2(b1.x, b1.x); bd[5] = pack2(b1.y, b1.y);
            bd[6] = pack2(b1.z, b1.z); bd[7] = pack2(b1.w, b1.w);
            #pragma unroll
            for (int p = 0; p < 4; p++)
                #pragma unroll
                for (int j = 0; j < 8; j++)
                    fma2(acc2[p][j], ap[p], bd[j]);
        }
        if (kb < FIN_ / BK - 1) {
            const int nb = buf ^ 1;
            S.As[nb][lk + 0][lr] = ra0.x; S.As[nb][lk + 1][lr] = ra0.y;
            S.As[nb][lk + 2][lr] = ra0.z; S.As[nb][lk + 3][lr] = ra0.w;
            S.As[nb][lk + 4][lr] = ra1.x; S.As[nb][lk + 5][lr] = ra1.y;
            S.As[nb][lk + 6][lr] = ra1.z; S.As[nb][lk + 7][lr] = ra1.w;
            S.Bs[nb][lk + 0][lr] = rb0.x; S.Bs[nb][lk + 1][lr] = rb0.y;
            S.Bs[nb][lk + 2][lr] = rb0.z; S.Bs[nb][lk + 3][lr] = rb0.w;
            S.Bs[nb][lk + 4][lr] = rb1.x; S.Bs[nb][lk + 5][lr] = rb1.y;
            S.Bs[nb][lk + 6][lr] = rb1.z; S.Bs[nb][lk + 7][lr] = rb1.w;
            __syncthreads();
        }
    }

    #pragma unroll
    for (int i = 0; i < 8; i++)
        #pragma unroll
        for (int j = 0; j < 8; j++) {
            float lo, hi;
            unpack2(acc2[i >> 1][j], lo, hi);
            acc[i][j] = (i & 1) ? hi : lo;
        }
}

__device__ __forceinline__ int acc_row(int bm, int ty, int i) {
    return bm + ((i < 4) ? (ty * 4 + i) : (64 + ty * 4 + (i - 4)));
}

// -------------------- CSR build (distributed global atomics) ----------------
__global__ void zero_cnt_kernel() {
    int i = blockIdx.x * blockDim.x + threadIdx.x;
    if (i < M_TOTAL) g_cnt[i] = 0;
}
__global__ void hist_kernel(const int* __restrict__ EI) {
    int idx = blockIdx.x * blockDim.x + threadIdx.x;
    if (idx >= B_ * E_) return;
    int b = idx / E_, e = idx - b * E_;
    int trg = EI[b * 2 * E_ + E_ + e];
    atomicAdd(&g_cnt[b * N_ + trg], 1);
}
// one block per batch, 1024 threads, 10 bins per thread
__global__ void scan_kernel() {
    __shared__ int psum[1024];
    const int b = blockIdx.x, t = threadIdx.x;
    const int base = b * N_;
    int lo = t * 10;
    int hi = lo + 10 < N_ ? lo + 10 : N_;
    int loc[10];
    int s = 0;
    for (int i = lo; i < hi; i++) { loc[i - lo] = s; s += g_cnt[base + i]; }
    psum[t] = s;
    __syncthreads();
    for (int off = 1; off < 1024; off <<= 1) {
        int v = (t >= off) ? psum[t - off] : 0;
        __syncthreads();
        psum[t] += v;
        __syncthreads();
    }
    int offset = (t > 0) ? psum[t - 1] : 0;
    for (int i = lo; i < hi; i++) {
        int r = offset + loc[i - lo];
        g_rowptr[base + i] = r;
        g_cursor[base + i] = r;
    }
}
__global__ void place_kernel(const int* __restrict__ EI) {
    int idx = blockIdx.x * blockDim.x + threadIdx.x;
    if (idx >= B_ * E_) return;
    int b = idx / E_, e = idx - b * E_;
    int src = EI[b * 2 * E_ + e];
    int trg = EI[b * 2 * E_ + E_ + e];
    int slot = atomicAdd(&g_cursor[b * N_ + trg], 1);
    g_elist[b * E_ + slot] = make_int2(e, src);
}

// -------------------- K1: proj = x@W^T + fused logits ----------------------
__global__ void __launch_bounds__(256, 2)
gemm0_kernel(const float* __restrict__ X, const float* __restrict__ W,
             const float* __restrict__ a_src, const float* __restrict__ a_trg) {
    __shared__ SmemGemm S;
    const int t = threadIdx.x;
    const int bm = blockIdx.y * BM, bn = blockIdx.x * BN;

    float acc[8][8];
    gemm_tile(X, W, bm, bn, S, acc);

    const int ty = t >> 4, tx = t & 15;
    const int h0 = (bn >> 5) + (tx >> 3);
    const int h1 = h0 + 2;
    const int cq = (tx & 7) * 4;
    float4 as0 = *reinterpret_cast<const float4*>(a_src + h0 * 32 + cq);
    float4 at0 = *reinterpret_cast<const float4*>(a_trg + h0 * 32 + cq);
    float4 as1 = *reinterpret_cast<const float4*>(a_src + h1 * 32 + cq);
    float4 at1 = *reinterpret_cast<const float4*>(a_trg + h1 * 32 + cq);

    #pragma unroll
    for (int i = 0; i < 8; i++) {
        int row = acc_row(bm, ty, i);
        bool ok = row < M_TOTAL;
        if (ok) {
            *reinterpret_cast<float4*>(g_proj + (size_t)row * FIN_ + bn + tx * 4) =
                make_float4(acc[i][0], acc[i][1], acc[i][2], acc[i][3]);
            *reinterpret_cast<float4*>(g_proj + (size_t)row * FIN_ + bn + 64 + tx * 4) =
                make_float4(acc[i][4], acc[i][5], acc[i][6], acc[i][7]);
        }
        float ss0 = acc[i][0] * as0.x + acc[i][1] * as0.y + acc[i][2] * as0.z + acc[i][3] * as0.w;
        float st0 = acc[i][0] * at0.x + acc[i][1] * at0.y + acc[i][2] * at0.z + acc[i][3] * at0.w;
        float ss1 = acc[i][4] * as1.x + acc[i][5] * as1.y + acc[i][6] * as1.z + acc[i][7] * as1.w;
        float st1 = acc[i][4] * at1.x + acc[i][5] * at1.y + acc[i][6] * at1.z + acc[i][7] * at1.w;
        #pragma unroll
        for (int o = 1; o <= 4; o <<= 1) {
            ss0 += __shfl_xor_sync(0xFFFFFFFFu, ss0, o);
            st0 += __shfl_xor_sync(0xFFFFFFFFu, st0, o);
            ss1 += __shfl_xor_sync(0xFFFFFFFFu, ss1, o);
            st1 += __shfl_xor_sync(0xFFFFFFFFu, st1, o);
        }
        if (ok && (tx & 7) == 0) {
            g_ssrc[row * H_ + h0] = ss0;
            g_strg[row * H_ + h0] = st0;
            g_ssrc[row * H_ + h1] = ss1;
            g_strg[row * H_ + h1] = st1;
        }
    }
}

// -------------------- K2a: relagg = segsum(rel), 8-edge unroll --------------
__global__ void __launch_bounds__(256)
gather_rel_kernel(const float* __restrict__ rel) {
    const int gw   = (blockIdx.x * 256 + threadIdx.x) >> 5;
    const int node = gw >> 1;
    const int w    = gw & 1;
    const int lane = threadIdx.x & 31;
    if (node >= M_TOTAL) return;
    const int b = node / N_;
    const int start = g_rowptr[node];
    const int cnt = g_cnt[node];
    const int2* elist = g_elist + (size_t)b * E_ + start;
    const float* relb = rel + (size_t)b * E_ * FIN_ + w * 128 + lane * 4;

    float4 aR = make_float4(0.f, 0.f, 0.f, 0.f);
    int i = 0;
    for (; i + 8 <= cnt; i += 8) {
        int e[8];
        #pragma unroll
        for (int u = 0; u < 8; u++) e[u] = elist[i + u].x;
        float4 r[8];
        #pragma unroll
        for (int u = 0; u < 8; u++)
            r[u] = *reinterpret_cast<const float4*>(relb + (size_t)e[u] * FIN_);
        #pragma unroll
        for (int u = 0; u < 8; u++) {
            aR.x += r[u].x; aR.y += r[u].y; aR.z += r[u].z; aR.w += r[u].w;
        }
    }
    if (i + 4 <= cnt) {
        int e0 = elist[i].x, e1 = elist[i + 1].x, e2 = elist[i + 2].x, e3 = elist[i + 3].x;
        float4 r0 = *reinterpret_cast<const float4*>(relb + (size_t)e0 * FIN_);
        float4 r1 = *reinterpret_cast<const float4*>(relb + (size_t)e1 * FIN_);
        float4 r2 = *reinterpret_cast<const float4*>(relb + (size_t)e2 * FIN_);
        float4 r3 = *reinterpret_cast<const float4*>(relb + (size_t)e3 * FIN_);
        aR.x += (r0.x + r1.x) + (r2.x + r3.x);
        aR.y += (r0.y + r1.y) + (r2.y + r3.y);
        aR.z += (r0.z + r1.z) + (r2.z + r3.z);
        aR.w += (r0.w + r1.w) + (r2.w + r3.w);
        i += 4;
    }
    for (; i < cnt; i++) {
        float4 r0 = *reinterpret_cast<const float4*>(relb + (size_t)elist[i].x * FIN_);
        aR.x += r0.x; aR.y += r0.y; aR.z += r0.z; aR.w += r0.w;
    }
    *reinterpret_cast<float4*>(g_relagg + (size_t)node * FIN_ + w * 128 + lane * 4) = aR;
}

// -------------------- K2b: numer = segsum(att*proj[src]), 8-edge unroll -----
__device__ __forceinline__ float lrexp(float s) {
    return __expf((s > 0.f) ? s : 0.2f * s);
}
__global__ void __launch_bounds__(256)
gather_att_kernel() {
    const int gw   = (blockIdx.x * 256 + threadIdx.x) >> 5;
    const int node = gw >> 1;
    const int w    = gw & 1;
    const int lane = threadIdx.x & 31;
    if (node >= M_TOTAL) return;
    const int b = node / N_;
    const int start = g_rowptr[node];
    const int cnt = g_cnt[node];
    const int2* elist = g_elist + (size_t)b * E_ + start;
    const float* ssrcb = g_ssrc + (size_t)b * N_ * H_;

    // pass 1: denom for heads w*4..w*4+3 (8 edges per iter)
    const int hh = w * 4 + (lane & 3);
    float my_strg = g_strg[node * H_ + hh];
    float denom = 0.f;
    for (int i = 0; i < cnt; i += 8) {
        int j = i + (lane >> 2);
        if (j < cnt)
            denom += lrexp(ssrcb[elist[j].y * H_ + hh] + my_strg);
    }
    denom += __shfl_xor_sync(0xFFFFFFFFu, denom, 4);
    denom += __shfl_xor_sync(0xFFFFFFFFu, denom, 8);
    denom += __shfl_xor_sync(0xFFFFFFFFu, denom, 16);
    const int mh = w * 4 + (lane >> 3);
    float inv_dh = 1.0f / (__shfl_sync(0xFFFFFFFFu, denom, lane >> 3) + 1e-16f);
    float strg_h = __shfl_sync(0xFFFFFFFFu, my_strg, lane >> 3);

    // pass 2: att-weighted proj accumulation (proj is L2-resident)
    const float* projb = g_proj + (size_t)b * N_ * FIN_ + w * 128 + lane * 4;
    float4 aN = make_float4(0.f, 0.f, 0.f, 0.f);
    int i = 0;
    for (; i + 8 <= cnt; i += 8) {
        int s[8];
        #pragma unroll
        for (int u = 0; u < 8; u++) s[u] = elist[i + u].y;
        float4 p[8];
        #pragma unroll
        for (int u = 0; u < 8; u++)
            p[u] = *reinterpret_cast<const float4*>(projb + (size_t)s[u] * FIN_);
        float tt[8];
        #pragma unroll
        for (int u = 0; u < 8; u++)
            tt[u] = lrexp(ssrcb[s[u] * H_ + mh] + strg_h) * inv_dh;
        #pragma unroll
        for (int u = 0; u < 8; u++) {
            aN.x += tt[u] * p[u].x; aN.y += tt[u] * p[u].y;
            aN.z += tt[u] * p[u].z; aN.w += tt[u] * p[u].w;
        }
    }
    if (i + 4 <= cnt) {
        int s0 = elist[i].y, s1 = elist[i + 1].y, s2 = elist[i + 2].y, s3 = elist[i + 3].y;
        float t0 = lrexp(ssrcb[s0 * H_ + mh] + strg_h) * inv_dh;
        float t1 = lrexp(ssrcb[s1 * H_ + mh] + strg_h) * inv_dh;
        float t2 = lrexp(ssrcb[s2 * H_ + mh] + strg_h) * inv_dh;
        float t3 = lrexp(ssrcb[s3 * H_ + mh] + strg_h) * inv_dh;
        float4 p0 = *reinterpret_cast<const float4*>(projb + (size_t)s0 * FIN_);
        float4 p1 = *reinterpret_cast<const float4*>(projb + (size_t)s1 * FIN_);
        float4 p2 = *reinterpret_cast<const float4*>(projb + (size_t)s2 * FIN_);
        float4 p3 = *reinterpret_cast<const float4*>(projb + (size_t)s3 * FIN_);
        aN.x += (t0 * p0.x + t1 * p1.x) + (t2 * p2.x + t3 * p3.x);
        aN.y += (t0 * p0.y + t1 * p1.y) + (t2 * p2.y + t3 * p3.y);
        aN.z += (t0 * p0.z + t1 * p1.z) + (t2 * p2.z + t3 * p3.z);
        aN.w += (t0 * p0.w + t1 * p1.w) + (t2 * p2.w + t3 * p3.w);
        i += 4;
    }
    for (; i < cnt; i++) {
        int s0 = elist[i].y;
        float t0 = lrexp(ssrcb[s0 * H_ + mh] + strg_h) * inv_dh;
        float4 p0 = *reinterpret_cast<const float4*>(projb + (size_t)s0 * FIN_);
        aN.x += t0 * p0.x; aN.y += t0 * p0.y; aN.z += t0 * p0.z; aN.w += t0 * p0.w;
    }
    *reinterpret_cast<float4*>(g_numer + (size_t)node * FIN_ + w * 128 + lane * 4) = aN;
}

// -------------------- K3a: pre = relagg@W^T + x + bias (no numer) ----------
__global__ void __launch_bounds__(256, 2)
gemm1_pre_kernel(const float* __restrict__ W, const float* __restrict__ X,
                 const float* __restrict__ bias) {
    __shared__ SmemGemm S;
    const int t = threadIdx.x;
    const int bm = blockIdx.y * BM, bn = blockIdx.x * BN;

    float acc[8][8];
    gemm_tile(g_relagg, W, bm, bn, S, acc);

    const int ty = t >> 4, tx = t & 15;
    const int c0 = bn + tx * 4, c1 = bn + 64 + tx * 4;
    float4 bb0 = *reinterpret_cast<const float4*>(bias + c0);
    float4 bb1 = *reinterpret_cast<const float4*>(bias + c1);
    #pragma unroll
    for (int i = 0; i < 8; i++) {
        int row = acc_row(bm, ty, i);
        if (row >= M_TOTAL) continue;
        #pragma unroll
        for (int half = 0; half < 2; half++) {
            int col = half ? c1 : c0;
            float4 bbv = half ? bb1 : bb0;
            const float* ap = &acc[i][half * 4];
            float4 xv = *reinterpret_cast<const float4*>(X + (size_t)row * FIN_ + col);
            float v0 = ap[0] + xv.x + bbv.x;
            float v1 = ap[1] + xv.y + bbv.y;
            float v2 = ap[2] + xv.z + bbv.z;
            float v3 = ap[3] + xv.w + bbv.w;
            *reinterpret_cast<float4*>(g_pre + (size_t)row * FIN_ + col) =
                make_float4(v0, v1, v2, v3);
        }
    }
}

// -------------------- K3b: out = elu(pre + numer) ---------------------------
__global__ void __launch_bounds__(256)
combine_kernel(float* __restrict__ out) {
    int idx = blockIdx.x * 256 + threadIdx.x;  // float4 index
    if (idx >= M_TOTAL * FIN_ / 4) return;
    float4 pv = reinterpret_cast<const float4*>(g_pre)[idx];
    float4 nv = reinterpret_cast<const float4*>(g_numer)[idx];
    float v0 = pv.x + nv.x, v1 = pv.y + nv.y, v2 = pv.z + nv.z, v3 = pv.w + nv.w;
    v0 = (v0 > 0.f) ? v0 : (__expf(v0) - 1.f);
    v1 = (v1 > 0.f) ? v1 : (__expf(v1) - 1.f);
    v2 = (v2 > 0.f) ? v2 : (__expf(v2) - 1.f);
    v3 = (v3 > 0.f) ? v3 : (__expf(v3) - 1.f);
    reinterpret_cast<float4*>(out)[idx] = make_float4(v0, v1, v2, v3);
}

// -------------------- launch ------------------------------------------------
extern "C" void kernel_launch(void* const* d_in, const int* in_sizes, int n_in,
                              void* d_out, int out_size) {
    const float* x     = (const float*)d_in[0];
    const int*   EI    = (const int*)  d_in[1];
    const float* rel   = (const float*)d_in[2];
    const float* W     = (const float*)d_in[3];
    const float* a_src = (const float*)d_in[4];
    const float* a_trg = (const float*)d_in[5];
    const float* bias  = (const float*)d_in[6];
    float* out = (float*)d_out;

    // One-time stream/event setup (no device memory allocation).
    static cudaStream_t s_side = nullptr;
    static cudaEvent_t ev_fork = nullptr, ev_sort = nullptr, ev_pre = nullptr;
    if (s_side == nullptr) {
        cudaStreamCreateWithFlags(&s_side, cudaStreamNonBlocking);
        cudaEventCreateWithFlags(&ev_fork, cudaEventDisableTiming);
        cudaEventCreateWithFlags(&ev_sort, cudaEventDisableTiming);
        cudaEventCreateWithFlags(&ev_pre, cudaEventDisableTiming);
    }

    dim3 ggrid(FIN_ / BN, (M_TOTAL + BM - 1) / BM);   // (2, 313)
    const int gblk = (M_TOTAL * 2 * 32 + 255) / 256;  // gather grids

    // Side stream: sort -> gather_rel -> gemm1_pre.
    cudaEventRecord(ev_fork, 0);
    cudaStreamWaitEvent(s_side, ev_fork, 0);
    zero_cnt_kernel<<<(M_TOTAL + 255) / 256, 256, 0, s_side>>>();
    hist_kernel<<<(B_ * E_ + 255) / 256, 256, 0, s_side>>>(EI);
    scan_kernel<<<B_, 1024, 0, s_side>>>();
    place_kernel<<<(B_ * E_ + 255) / 256, 256, 0, s_side>>>(EI);
    cudaEventRecord(ev_sort, s_side);
    gather_rel_kernel<<<gblk, 256, 0, s_side>>>(rel);
    gemm1_pre_kernel<<<ggrid, 256, 0, s_side>>>(W, x, bias);
    cudaEventRecord(ev_pre, s_side);

    // Main stream: gemm0 -> gather_att (overlaps side's gather_rel/gemm1_pre).
    gemm0_kernel<<<ggrid, 256>>>(x, W, a_src, a_trg);
    cudaStreamWaitEvent(0, ev_sort, 0);
    gather_att_kernel<<<gblk, 256>>>();

    // Final combine after both branches.
    cudaStreamWaitEvent(0, ev_pre, 0);
    combine_kernel<<<(M_TOTAL * FIN_ / 4 + 255) / 256, 256>>>(out);
}

// round 16
// speedup vs baseline: 1.0324x; 1.0324x over previous
#include <cuda_runtime.h>
#include <math.h>
#include <cstdint>

// Problem constants
#define B_   4
#define N_   10000
#define E_   100000
#define H_   8
#define FIN_ 256
#define M_TOTAL 40000

// GEMM tiling
#define BM 128
#define BN 128
#define BK 16

// -------------------- scratch (device globals) ------------------------------
__device__ float g_proj  [M_TOTAL * FIN_];
__device__ float g_numer [M_TOTAL * FIN_];
__device__ float g_relagg[M_TOTAL * FIN_];
__device__ float g_pre   [M_TOTAL * FIN_];
__device__ float g_ssrc  [M_TOTAL * H_];
__device__ float g_strg  [M_TOTAL * H_];
__device__ int   g_cnt   [M_TOTAL];
__device__ int   g_rowptr[M_TOTAL];
__device__ int   g_cursor[M_TOTAL];
__device__ int2  g_elist [B_ * E_];     // (edge id, src) sorted by trg

// -------------------- f32x2 packed helpers ----------------------------------
__device__ __forceinline__ unsigned long long pack2(float x, float y) {
    unsigned long long r;
    asm("mov.b64 %0, {%1, %2};" : "=l"(r) : "f"(x), "f"(y));
    return r;
}
__device__ __forceinline__ void unpack2(unsigned long long v, float& x, float& y) {
    asm("mov.b64 {%0, %1}, %2;" : "=f"(x), "=f"(y) : "l"(v));
}
__device__ __forceinline__ void fma2(unsigned long long& d,
                                     unsigned long long a, unsigned long long b) {
    asm("fma.rn.f32x2 %0, %1, %2, %0;" : "+l"(d) : "l"(a), "l"(b));
}

// -------------------- GEMM core ---------------------------------------------
struct SmemGemm {
    float As[2][BK][BM];
    float Bs[2][BK][BN];
};  // 32768 bytes

__device__ __forceinline__ void gemm_tile(const float* __restrict__ A,
                                          const float* __restrict__ Wt,
                                          int bm, int bn, SmemGemm& S,
                                          float acc[8][8]) {
    const int t  = threadIdx.x;
    const int lr = t & 127, lk = (t >> 7) * 8;
    const int ty = t >> 4,  tx = t & 15;

    const bool aval = (bm + lr) < M_TOTAL;
    const float* Arow = A  + (size_t)(bm + lr) * FIN_ + lk;
    const float* Brow = Wt + (size_t)(bn + lr) * FIN_ + lk;

    const float4 fz = make_float4(0.f, 0.f, 0.f, 0.f);
    float4 ra0 = aval ? *reinterpret_cast<const float4*>(Arow)     : fz;
    float4 ra1 = aval ? *reinterpret_cast<const float4*>(Arow + 4) : fz;
    float4 rb0 = *reinterpret_cast<const float4*>(Brow);
    float4 rb1 = *reinterpret_cast<const float4*>(Brow + 4);

    unsigned long long acc2[4][8];
    #pragma unroll
    for (int p = 0; p < 4; p++)
        #pragma unroll
        for (int j = 0; j < 8; j++) acc2[p][j] = 0ull;

    S.As[0][lk + 0][lr] = ra0.x; S.As[0][lk + 1][lr] = ra0.y;
    S.As[0][lk + 2][lr] = ra0.z; S.As[0][lk + 3][lr] = ra0.w;
    S.As[0][lk + 4][lr] = ra1.x; S.As[0][lk + 5][lr] = ra1.y;
    S.As[0][lk + 6][lr] = ra1.z; S.As[0][lk + 7][lr] = ra1.w;
    S.Bs[0][lk + 0][lr] = rb0.x; S.Bs[0][lk + 1][lr] = rb0.y;
    S.Bs[0][lk + 2][lr] = rb0.z; S.Bs[0][lk + 3][lr] = rb0.w;
    S.Bs[0][lk + 4][lr] = rb1.x; S.Bs[0][lk + 5][lr] = rb1.y;
    S.Bs[0][lk + 6][lr] = rb1.z; S.Bs[0][lk + 7][lr] = rb1.w;
    __syncthreads();

    #pragma unroll 1
    for (int kb = 0; kb < FIN_ / BK; kb++) {
        const int buf = kb & 1;
        if (kb < FIN_ / BK - 1) {
            const float* An = Arow + (kb + 1) * BK;
            const float* Bn = Brow + (kb + 1) * BK;
            ra0 = aval ? *reinterpret_cast<const float4*>(An)     : fz;
            ra1 = aval ? *reinterpret_cast<const float4*>(An + 4) : fz;
            rb0 = *reinterpret_cast<const float4*>(Bn);
            rb1 = *reinterpret_cast<const float4*>(Bn + 4);
        }
        #pragma unroll
        for (int k = 0; k < BK; k++) {
            float4 a0 = *reinterpret_cast<const float4*>(&S.As[buf][k][ty * 4]);
            float4 a1 = *reinterpret_cast<const float4*>(&S.As[buf][k][64 + ty * 4]);
            float4 b0 = *reinterpret_cast<const float4*>(&S.Bs[buf][k][tx * 4]);
            float4 b1 = *reinterpret_cast<const float4*>(&S.Bs[buf][k][64 + tx * 4]);
            unsigned long long ap[4];
            ap[0] = pack2(a0.x, a0.y); ap[1] = pack2(a0.z, a0.w);
            ap[2] = pack2(a1.x, a1.y); ap[3] = pack2(a1.z, a1.w);
            unsigned long long bd[8];
            bd[0] = pack2(b0.x, b0.x); bd[1] = pack2(b0.y, b0.y);
            bd[2] = pack2(b0.z, b0.z); bd[3] = pack2(b0.w, b0.w);
            bd[4] = pack2(b1.x, b1.x); bd[5] = pack2(b1.y, b1.y);
            bd[6] = pack2(b1.z, b1.z); bd[7] = pack2(b1.w, b1.w);
            #pragma unroll
            for (int p = 0; p < 4; p++)
                #pragma unroll
                for (int j = 0; j < 8; j++)
                    fma2(acc2[p][j], ap[p], bd[j]);
        }
        if (kb < FIN_ / BK - 1) {
            const int nb = buf ^ 1;
            S.As[nb][lk + 0][lr] = ra0.x; S.As[nb][lk + 1][lr] = ra0.y;
            S.As[nb][lk + 2][lr] = ra0.z; S.As[nb][lk + 3][lr] = ra0.w;
            S.As[nb][lk + 4][lr] = ra1.x; S.As[nb][lk + 5][lr] = ra1.y;
            S.As[nb][lk + 6][lr] = ra1.z; S.As[nb][lk + 7][lr] = ra1.w;
            S.Bs[nb][lk + 0][lr] = rb0.x; S.Bs[nb][lk + 1][lr] = rb0.y;
            S.Bs[nb][lk + 2][lr] = rb0.z; S.Bs[nb][lk + 3][lr] = rb0.w;
            S.Bs[nb][lk + 4][lr] = rb1.x; S.Bs[nb][lk + 5][lr] = rb1.y;
            S.Bs[nb][lk + 6][lr] = rb1.z; S.Bs[nb][lk + 7][lr] = rb1.w;
            __syncthreads();
        }
    }

    #pragma unroll
    for (int i = 0; i < 8; i++)
        #pragma unroll
        for (int j = 0; j < 8; j++) {
            float lo, hi;
            unpack2(acc2[i >> 1][j], lo, hi);
            acc[i][j] = (i & 1) ? hi : lo;
        }
}

__device__ __forceinline__ int acc_row(int bm, int ty, int i) {
    return bm + ((i < 4) ? (ty * 4 + i) : (64 + ty * 4 + (i - 4)));
}

// -------------------- CSR build (distributed global atomics) ----------------
__global__ void zero_cnt_kernel() {
    int i = blockIdx.x * blockDim.x + threadIdx.x;
    if (i < M_TOTAL) g_cnt[i] = 0;
}
__global__ void hist_kernel(const int* __restrict__ EI) {
    int idx = blockIdx.x * blockDim.x + threadIdx.x;
    if (idx >= B_ * E_) return;
    int b = idx / E_, e = idx - b * E_;
    int trg = EI[b * 2 * E_ + E_ + e];
    atomicAdd(&g_cnt[b * N_ + trg], 1);
}
// one block per batch, 1024 threads, 10 bins per thread
__global__ void scan_kernel() {
    __shared__ int psum[1024];
    const int b = blockIdx.x, t = threadIdx.x;
    const int base = b * N_;
    int lo = t * 10;
    int hi = lo + 10 < N_ ? lo + 10 : N_;
    int loc[10];
    int s = 0;
    for (int i = lo; i < hi; i++) { loc[i - lo] = s; s += g_cnt[base + i]; }
    psum[t] = s;
    __syncthreads();
    for (int off = 1; off < 1024; off <<= 1) {
        int v = (t >= off) ? psum[t - off] : 0;
        __syncthreads();
        psum[t] += v;
        __syncthreads();
    }
    int offset = (t > 0) ? psum[t - 1] : 0;
    for (int i = lo; i < hi; i++) {
        int r = offset + loc[i - lo];
        g_rowptr[base + i] = r;
        g_cursor[base + i] = r;
    }
}
__global__ void place_kernel(const int* __restrict__ EI) {
    int idx = blockIdx.x * blockDim.x + threadIdx.x;
    if (idx >= B_ * E_) return;
    int b = idx / E_, e = idx - b * E_;
    int src = EI[b * 2 * E_ + e];
    int trg = EI[b * 2 * E_ + E_ + e];
    int slot = atomicAdd(&g_cursor[b * N_ + trg], 1);
    g_elist[b * E_ + slot] = make_int2(e, src);
}

// -------------------- K1: proj = x@W^T + fused logits ----------------------
__global__ void __launch_bounds__(256, 2)
gemm0_kernel(const float* __restrict__ X, const float* __restrict__ W,
             const float* __restrict__ a_src, const float* __restrict__ a_trg) {
    __shared__ SmemGemm S;
    const int t = threadIdx.x;
    const int bm = blockIdx.y * BM, bn = blockIdx.x * BN;

    float acc[8][8];
    gemm_tile(X, W, bm, bn, S, acc);

    const int ty = t >> 4, tx = t & 15;
    const int h0 = (bn >> 5) + (tx >> 3);
    const int h1 = h0 + 2;
    const int cq = (tx & 7) * 4;
    float4 as0 = *reinterpret_cast<const float4*>(a_src + h0 * 32 + cq);
    float4 at0 = *reinterpret_cast<const float4*>(a_trg + h0 * 32 + cq);
    float4 as1 = *reinterpret_cast<const float4*>(a_src + h1 * 32 + cq);
    float4 at1 = *reinterpret_cast<const float4*>(a_trg + h1 * 32 + cq);

    #pragma unroll
    for (int i = 0; i < 8; i++) {
        int row = acc_row(bm, ty, i);
        bool ok = row < M_TOTAL;
        if (ok) {
            *reinterpret_cast<float4*>(g_proj + (size_t)row * FIN_ + bn + tx * 4) =
                make_float4(acc[i][0], acc[i][1], acc[i][2], acc[i][3]);
            *reinterpret_cast<float4*>(g_proj + (size_t)row * FIN_ + bn + 64 + tx * 4) =
                make_float4(acc[i][4], acc[i][5], acc[i][6], acc[i][7]);
        }
        float ss0 = acc[i][0] * as0.x + acc[i][1] * as0.y + acc[i][2] * as0.z + acc[i][3] * as0.w;
        float st0 = acc[i][0] * at0.x + acc[i][1] * at0.y + acc[i][2] * at0.z + acc[i][3] * at0.w;
        float ss1 = acc[i][4] * as1.x + acc[i][5] * as1.y + acc[i][6] * as1.z + acc[i][7] * as1.w;
        float st1 = acc[i][4] * at1.x + acc[i][5] * at1.y + acc[i][6] * at1.z + acc[i][7] * at1.w;
        #pragma unroll
        for (int o = 1; o <= 4; o <<= 1) {
            ss0 += __shfl_xor_sync(0xFFFFFFFFu, ss0, o);
            st0 += __shfl_xor_sync(0xFFFFFFFFu, st0, o);
            ss1 += __shfl_xor_sync(0xFFFFFFFFu, ss1, o);
            st1 += __shfl_xor_sync(0xFFFFFFFFu, st1, o);
        }
        if (ok && (tx & 7) == 0) {
            g_ssrc[row * H_ + h0] = ss0;
            g_strg[row * H_ + h0] = st0;
            g_ssrc[row * H_ + h1] = ss1;
            g_strg[row * H_ + h1] = st1;
        }
    }
}

// -------------------- K2a: relagg = segsum(rel), streaming loads ------------
__global__ void __launch_bounds__(256)
gather_rel_kernel(const float* __restrict__ rel) {
    const int gw   = (blockIdx.x * 256 + threadIdx.x) >> 5;
    const int node = gw >> 1;
    const int w    = gw & 1;
    const int lane = threadIdx.x & 31;
    if (node >= M_TOTAL) return;
    const int b = node / N_;
    const int start = g_rowptr[node];
    const int cnt = g_cnt[node];
    const int2* elist = g_elist + (size_t)b * E_ + start;
    const float* relb = rel + (size_t)b * E_ * FIN_ + w * 128 + lane * 4;

    float4 aR = make_float4(0.f, 0.f, 0.f, 0.f);
    int i = 0;
    for (; i + 4 <= cnt; i += 4) {
        int e0 = elist[i].x, e1 = elist[i + 1].x, e2 = elist[i + 2].x, e3 = elist[i + 3].x;
        // __ldcs: evict-first streaming loads — rel has zero reuse; keep L2 for
        // proj/relagg consumed by the concurrently-running kernels.
        float4 r0 = __ldcs(reinterpret_cast<const float4*>(relb + (size_t)e0 * FIN_));
        float4 r1 = __ldcs(reinterpret_cast<const float4*>(relb + (size_t)e1 * FIN_));
        float4 r2 = __ldcs(reinterpret_cast<const float4*>(relb + (size_t)e2 * FIN_));
        float4 r3 = __ldcs(reinterpret_cast<const float4*>(relb + (size_t)e3 * FIN_));
        aR.x += (r0.x + r1.x) + (r2.x + r3.x);
        aR.y += (r0.y + r1.y) + (r2.y + r3.y);
        aR.z += (r0.z + r1.z) + (r2.z + r3.z);
        aR.w += (r0.w + r1.w) + (r2.w + r3.w);
    }
    for (; i < cnt; i++) {
        float4 r0 = __ldcs(reinterpret_cast<const float4*>(relb + (size_t)elist[i].x * FIN_));
        aR.x += r0.x; aR.y += r0.y; aR.z += r0.z; aR.w += r0.w;
    }
    *reinterpret_cast<float4*>(g_relagg + (size_t)node * FIN_ + w * 128 + lane * 4) = aR;
}

// -------------------- K2b: numer = segsum(att*proj[src]) --------------------
__device__ __forceinline__ float lrexp(float s) {
    return __expf((s > 0.f) ? s : 0.2f * s);
}
__global__ void __launch_bounds__(256)
gather_att_kernel() {
    const int gw   = (blockIdx.x * 256 + threadIdx.x) >> 5;
    const int node = gw >> 1;
    const int w    = gw & 1;
    const int lane = threadIdx.x & 31;
    if (node >= M_TOTAL) return;
    const int b = node / N_;
    const int start = g_rowptr[node];
    const int cnt = g_cnt[node];
    const int2* elist = g_elist + (size_t)b * E_ + start;
    const float* ssrcb = g_ssrc + (size_t)b * N_ * H_;

    // pass 1: denom for heads w*4..w*4+3 (8 edges per iter)
    const int hh = w * 4 + (lane & 3);
    float my_strg = g_strg[node * H_ + hh];
    float denom = 0.f;
    for (int i = 0; i < cnt; i += 8) {
        int j = i + (lane >> 2);
        if (j < cnt)
            denom += lrexp(ssrcb[elist[j].y * H_ + hh] + my_strg);
    }
    denom += __shfl_xor_sync(0xFFFFFFFFu, denom, 4);
    denom += __shfl_xor_sync(0xFFFFFFFFu, denom, 8);
    denom += __shfl_xor_sync(0xFFFFFFFFu, denom, 16);
    const int mh = w * 4 + (lane >> 3);
    float inv_dh = 1.0f / (__shfl_sync(0xFFFFFFFFu, denom, lane >> 3) + 1e-16f);
    float strg_h = __shfl_sync(0xFFFFFFFFu, my_strg, lane >> 3);

    // pass 2: att-weighted proj accumulation (proj is L2-resident)
    const float* projb = g_proj + (size_t)b * N_ * FIN_ + w * 128 + lane * 4;
    float4 aN = make_float4(0.f, 0.f, 0.f, 0.f);
    int i = 0;
    for (; i + 4 <= cnt; i += 4) {
        int s0 = elist[i].y, s1 = elist[i + 1].y, s2 = elist[i + 2].y, s3 = elist[i + 3].y;
        float t0 = lrexp(ssrcb[s0 * H_ + mh] + strg_h) * inv_dh;
        float t1 = lrexp(ssrcb[s1 * H_ + mh] + strg_h) * inv_dh;
        float t2 = lrexp(ssrcb[s2 * H_ + mh] + strg_h) * inv_dh;
        float t3 = lrexp(ssrcb[s3 * H_ + mh] + strg_h) * inv_dh;
        float4 p0 = *reinterpret_cast<const float4*>(projb + (size_t)s0 * FIN_);
        float4 p1 = *reinterpret_cast<const float4*>(projb + (size_t)s1 * FIN_);
        float4 p2 = *reinterpret_cast<const float4*>(projb + (size_t)s2 * FIN_);
        float4 p3 = *reinterpret_cast<const float4*>(projb + (size_t)s3 * FIN_);
        aN.x += (t0 * p0.x + t1 * p1.x) + (t2 * p2.x + t3 * p3.x);
        aN.y += (t0 * p0.y + t1 * p1.y) + (t2 * p2.y + t3 * p3.y);
        aN.z += (t0 * p0.z + t1 * p1.z) + (t2 * p2.z + t3 * p3.z);
        aN.w += (t0 * p0.w + t1 * p1.w) + (t2 * p2.w + t3 * p3.w);
    }
    for (; i < cnt; i++) {
        int s0 = elist[i].y;
        float t0 = lrexp(ssrcb[s0 * H_ + mh] + strg_h) * inv_dh;
        float4 p0 = *reinterpret_cast<const float4*>(projb + (size_t)s0 * FIN_);
        aN.x += t0 * p0.x; aN.y += t0 * p0.y; aN.z += t0 * p0.z; aN.w += t0 * p0.w;
    }
    *reinterpret_cast<float4*>(g_numer + (size_t)node * FIN_ + w * 128 + lane * 4) = aN;
}

// -------------------- K3a: pre = relagg@W^T + x + bias (no numer) ----------
__global__ void __launch_bounds__(256, 2)
gemm1_pre_kernel(const float* __restrict__ W, const float* __restrict__ X,
                 const float* __restrict__ bias) {
    __shared__ SmemGemm S;
    const int t = threadIdx.x;
    const int bm = blockIdx.y * BM, bn = blockIdx.x * BN;

    float acc[8][8];
    gemm_tile(g_relagg, W, bm, bn, S, acc);

    const int ty = t >> 4, tx = t & 15;
    const int c0 = bn + tx * 4, c1 = bn + 64 + tx * 4;
    float4 bb0 = *reinterpret_cast<const float4*>(bias + c0);
    float4 bb1 = *reinterpret_cast<const float4*>(bias + c1);
    #pragma unroll
    for (int i = 0; i < 8; i++) {
        int row = acc_row(bm, ty, i);
        if (row >= M_TOTAL) continue;
        #pragma unroll
        for (int half = 0; half < 2; half++) {
            int col = half ? c1 : c0;
            float4 bbv = half ? bb1 : bb0;
            const float* ap = &acc[i][half * 4];
            float4 xv = *reinterpret_cast<const float4*>(X + (size_t)row * FIN_ + col);
            float v0 = ap[0] + xv.x + bbv.x;
            float v1 = ap[1] + xv.y + bbv.y;
            float v2 = ap[2] + xv.z + bbv.z;
            float v3 = ap[3] + xv.w + bbv.w;
            *reinterpret_cast<float4*>(g_pre + (size_t)row * FIN_ + col) =
                make_float4(v0, v1, v2, v3);
        }
    }
}

// -------------------- K3b: out = elu(pre + numer) ---------------------------
__global__ void __launch_bounds__(256)
combine_kernel(float* __restrict__ out) {
    int idx = blockIdx.x * 256 + threadIdx.x;  // float4 index
    if (idx >= M_TOTAL * FIN_ / 4) return;
    float4 pv = reinterpret_cast<const float4*>(g_pre)[idx];
    float4 nv = reinterpret_cast<const float4*>(g_numer)[idx];
    float v0 = pv.x + nv.x, v1 = pv.y + nv.y, v2 = pv.z + nv.z, v3 = pv.w + nv.w;
    v0 = (v0 > 0.f) ? v0 : (__expf(v0) - 1.f);
    v1 = (v1 > 0.f) ? v1 : (__expf(v1) - 1.f);
    v2 = (v2 > 0.f) ? v2 : (__expf(v2) - 1.f);
    v3 = (v3 > 0.f) ? v3 : (__expf(v3) - 1.f);
    reinterpret_cast<float4*>(out)[idx] = make_float4(v0, v1, v2, v3);
}

// -------------------- launch ------------------------------------------------
extern "C" void kernel_launch(void* const* d_in, const int* in_sizes, int n_in,
                              void* d_out, int out_size) {
    const float* x     = (const float*)d_in[0];
    const int*   EI    = (const int*)  d_in[1];
    const float* rel   = (const float*)d_in[2];
    const float* W     = (const float*)d_in[3];
    const float* a_src = (const float*)d_in[4];
    const float* a_trg = (const float*)d_in[5];
    const float* bias  = (const float*)d_in[6];
    float* out = (float*)d_out;

    // One-time stream/event setup (no device memory allocation).
    static cudaStream_t s_side = nullptr;
    static cudaEvent_t ev_fork = nullptr, ev_sort = nullptr, ev_pre = nullptr;
    if (s_side == nullptr) {
        cudaStreamCreateWithFlags(&s_side, cudaStreamNonBlocking);
        cudaEventCreateWithFlags(&ev_fork, cudaEventDisableTiming);
        cudaEventCreateWithFlags(&ev_sort, cudaEventDisableTiming);
        cudaEventCreateWithFlags(&ev_pre, cudaEventDisableTiming);
    }

    dim3 ggrid(FIN_ / BN, (M_TOTAL + BM - 1) / BM);   // (2, 313)
    const int gblk = (M_TOTAL * 2 * 32 + 255) / 256;  // gather grids

    // Side stream: sort -> gather_rel -> gemm1_pre.
    cudaEventRecord(ev_fork, 0);
    cudaStreamWaitEvent(s_side, ev_fork, 0);
    zero_cnt_kernel<<<(M_TOTAL + 255) / 256, 256, 0, s_side>>>();
    hist_kernel<<<(B_ * E_ + 255) / 256, 256, 0, s_side>>>(EI);
    scan_kernel<<<B_, 1024, 0, s_side>>>();
    place_kernel<<<(B_ * E_ + 255) / 256, 256, 0, s_side>>>(EI);
    cudaEventRecord(ev_sort, s_side);
    gather_rel_kernel<<<gblk, 256, 0, s_side>>>(rel);
    gemm1_pre_kernel<<<ggrid, 256, 0, s_side>>>(W, x, bias);
    cudaEventRecord(ev_pre, s_side);

    // Main stream: gemm0 -> gather_att (overlaps side's gather_rel/gemm1_pre).
    gemm0_kernel<<<ggrid, 256>>>(x, W, a_src, a_trg);
    cudaStreamWaitEvent(0, ev_sort, 0);
    gather_att_kernel<<<gblk, 256>>>();

    // Final combine after both branches.
    cudaStreamWaitEvent(0, ev_pre, 0);
    combine_kernel<<<(M_TOTAL * FIN_ / 4 + 255) / 256, 256>>>(out);
}